// round 10
// baseline (speedup 1.0000x reference)
#include <cuda_runtime.h>
#include <cstdint>

#define N_NODES 12288
#define H_DIM   128
#define E_EDGES 393216
#define NEGVAL  (-1000000000.0f)
#define ROW4    (N_NODES / 4)          // 3072 float4 per row
#define CAP     256                    // bucket capacity (Poisson(32), max~65)
#define GRID    592                    // 148 SMs x 4 blocks -> exactly one wave
#define NTHREADS 512
#define TOTAL_THREADS (GRID * NTHREADS)  // 303104
#define TOTAL_WARPS   (GRID * 16)        // 9472

// Static scratch. g_cursor zero-init; self-restored each launch.
__device__ float g_d1[N_NODES];
__device__ float g_d2[N_NODES];
__device__ int   g_cursor[N_NODES];
__device__ int2  g_bucket[(size_t)N_NODES * CAP];  // (src_col, float_bits(value))

// Software grid barrier state. Epoch is monotonic across barrier uses AND
// graph replays -> no reset needed, deterministic.
__device__ unsigned          g_count = 0;
__device__ volatile unsigned g_epoch = 0;

// Sense-reversing grid barrier. Safe because grid==592 is exactly one
// resident wave (4 blocks/SM @ 48KB smem), so all blocks are co-scheduled.
__device__ __forceinline__ void grid_barrier() {
    __syncthreads();
    if (threadIdx.x == 0) {
        unsigned my = g_epoch;                   // read BEFORE arriving
        __threadfence();                         // release my phase's writes
        unsigned old = atomicAdd(&g_count, 1);
        if (old == GRID - 1) {
            g_count = 0;                         // safe: all arrived
            __threadfence();
            g_epoch = my + 1;                    // release
        } else {
            while (g_epoch == my) __nanosleep(32);
            __threadfence();                     // acquire
        }
    }
    __syncthreads();
}

// ---------------------------------------------------------------------------
// Fused persistent kernel: dots -> barrier -> place -> barrier -> fill+merge.
// ---------------------------------------------------------------------------
__global__ __launch_bounds__(NTHREADS, 4)
void fused_kernel(const float* __restrict__ h,
                  const float* __restrict__ W,
                  const float* __restrict__ b,
                  const int*   __restrict__ src,
                  const int*   __restrict__ dst,
                  const float* __restrict__ wts,
                  float4* __restrict__ out) {
    __shared__ float row[N_NODES];               // exactly 48 KB
    float4* row4 = (float4*)row;
    const int tid   = threadIdx.x;
    const int t     = (int)(blockIdx.x * NTHREADS + tid);
    const int lane  = tid & 31;
    const int gwarp = t >> 5;
    const float4 v  = make_float4(NEGVAL, NEGVAL, NEGVAL, NEGVAL);

    // ---- phase 1: per-node dots (1 warp/node, grid-warp-stride) ----
    {
        const float4* w14 = (const float4*)(W);
        const float4* w24 = (const float4*)(W + H_DIM);
        float4 w1 = __ldg(&w14[lane]);
        float4 w2 = __ldg(&w24[lane]);
        for (int n = gwarp; n < N_NODES; n += TOTAL_WARPS) {
            const float4* hr4 = (const float4*)(h + (size_t)n * H_DIM);
            float4 hv = __ldg(&hr4[lane]);
            float s1 = fmaf(hv.x, w1.x, fmaf(hv.y, w1.y, fmaf(hv.z, w1.z, hv.w * w1.w)));
            float s2 = fmaf(hv.x, w2.x, fmaf(hv.y, w2.y, fmaf(hv.z, w2.z, hv.w * w2.w)));
#pragma unroll
            for (int off = 16; off; off >>= 1) {
                s1 += __shfl_down_sync(0xffffffffu, s1, off);
                s2 += __shfl_down_sync(0xffffffffu, s2, off);
            }
            if (lane == 0) { g_d1[n] = s1; g_d2[n] = s2; }
        }
    }

    // prefill this block's smem row with NEG (independent of everything)
#pragma unroll
    for (int i = tid; i < ROW4; i += NTHREADS) row4[i] = v;

    grid_barrier();                              // d1/d2 visible everywhere

    // ---- phase 2: place edges with precomputed values ----
    {
        const float wlin = __ldg(&W[2 * H_DIM]);
        const float bias = __ldg(&b[0]);
        for (int e = t; e < E_EDGES; e += TOTAL_THREADS) {   // <=2 iters
            int   s = src[e];
            int   d = dst[e];
            float w = wts[e];
            float val = g_d1[d] + g_d2[s] + fmaf(w, wlin, bias);
            int pos = atomicAdd(&g_cursor[d], 1);
            if (pos < CAP)
                g_bucket[(size_t)d * CAP + pos] = make_int2(s, __float_as_int(val));
        }
    }

    grid_barrier();                              // buckets + cursors visible

    // ---- phase 3: fill + merge + stream out (R9-proven loop) ----
    bool first = true;
    for (int r = blockIdx.x; r < N_NODES; r += GRID) {
        int c   = g_cursor[r];                   // broadcast; hidden under fill
        int cnt = (c < CAP) ? c : CAP;

        if (!first) {
#pragma unroll
            for (int i = tid; i < ROW4; i += NTHREADS) row4[i] = v;
        }
        first = false;
        __syncthreads();                         // all cursor[r] reads done

        if (tid == 0) g_cursor[r] = 0;           // self-restore for next launch

        const int2* bkt = &g_bucket[(size_t)r * CAP];
        for (int i = tid; i < cnt; i += NTHREADS) {
            int2 ev = bkt[i];
            row[ev.x] = __int_as_float(ev.y);    // dup races benign
        }
        __syncthreads();

        float4* dstp = out + (size_t)r * ROW4;
#pragma unroll
        for (int i = tid; i < ROW4; i += NTHREADS) __stcs(&dstp[i], row4[i]);
        __syncthreads();                         // stores done before smem reuse
    }
}

// ---------------------------------------------------------------------------
// Launch. Input order (metadata): h, sources, dests, weights, W, b
// ---------------------------------------------------------------------------
extern "C" void kernel_launch(void* const* d_in, const int* in_sizes, int n_in,
                              void* d_out, int out_size) {
    const float* h       = (const float*)d_in[0];
    const int*   sources = (const int*)  d_in[1];
    const int*   dests   = (const int*)  d_in[2];
    const float* weights = (const float*)d_in[3];
    const float* W       = (const float*)d_in[4];
    const float* b       = (const float*)d_in[5];
    float*       out     = (float*)d_out;

    fused_kernel<<<GRID, NTHREADS>>>(h, W, b, sources, dests, weights,
                                     (float4*)out);
}